// round 10
// baseline (speedup 1.0000x reference)
#include <cuda_runtime.h>
#include <math.h>
#include <stdint.h>

typedef unsigned long long ull;
typedef unsigned short u16;
typedef signed char s8;

#define NN 4096
#define UN 256
#define BT 512
#define WCLIP 0.0859375f        // 5.5/64 clip for w_gcn quantization

// ================= helpers =================
__device__ __forceinline__ uint32_t smem_u32(const void* p){
    uint32_t a;
    asm("{ .reg .u64 t; cvta.to.shared.u64 t, %1; cvt.u32.u64 %0, t; }" : "=r"(a) : "l"(p));
    return a;
}
__device__ __forceinline__ void cpasync16(uint32_t daddr, const void* gptr){
    asm volatile("cp.async.cg.shared.global [%0], [%1], 16;" :: "r"(daddr), "l"(gptr));
}
#define CP_COMMIT asm volatile("cp.async.commit_group;" ::: "memory")
#define CP_WAIT0  asm volatile("cp.async.wait_group 0;" ::: "memory")

// fp16 hi/lo split helpers (kernels B/C — numerics unchanged)
__device__ __forceinline__ void split2h(float v0, float v1, uint32_t& hp, uint32_t& lp){
    u16 h0, h1, l0, l1;
    asm("cvt.rn.f16.f32 %0, %1;" : "=h"(h0) : "f"(v0));
    asm("cvt.rn.f16.f32 %0, %1;" : "=h"(h1) : "f"(v1));
    float f0, f1;
    asm("cvt.f32.f16 %0, %1;" : "=f"(f0) : "h"(h0));
    asm("cvt.f32.f16 %0, %1;" : "=f"(f1) : "h"(h1));
    asm("cvt.rn.f16.f32 %0, %1;" : "=h"(l0) : "f"(v0 - f0));
    asm("cvt.rn.f16.f32 %0, %1;" : "=h"(l1) : "f"(v1 - f1));
    asm("mov.b32 %0, {%1, %2};" : "=r"(hp) : "h"(h0), "h"(h1));
    asm("mov.b32 %0, {%1, %2};" : "=r"(lp) : "h"(l0), "h"(l1));
}
__device__ __forceinline__ void split1h(float v, u16& h, u16& l){
    u16 hb, lb;
    asm("cvt.rn.f16.f32 %0, %1;" : "=h"(hb) : "f"(v));
    float hf;
    asm("cvt.f32.f16 %0, %1;" : "=f"(hf) : "h"(hb));
    asm("cvt.rn.f16.f32 %0, %1;" : "=h"(lb) : "f"(v - hf));
    h = hb; l = lb;
}

__device__ __forceinline__ void mma16816h(float* d, const uint32_t* a, const uint32_t* b){
    asm volatile("mma.sync.aligned.m16n8k16.row.col.f32.f16.f16.f32 "
        "{%0,%1,%2,%3}, {%4,%5,%6,%7}, {%8,%9}, {%0,%1,%2,%3};"
        : "+f"(d[0]), "+f"(d[1]), "+f"(d[2]), "+f"(d[3])
        : "r"(a[0]), "r"(a[1]), "r"(a[2]), "r"(a[3]), "r"(b[0]), "r"(b[1]));
}
__device__ __forceinline__ void mma16832s8(int* d, const uint32_t* a, const uint32_t* b){
    asm volatile("mma.sync.aligned.m16n8k32.row.col.s32.s8.s8.s32 "
        "{%0,%1,%2,%3}, {%4,%5,%6,%7}, {%8,%9}, {%0,%1,%2,%3};"
        : "+r"(d[0]), "+r"(d[1]), "+r"(d[2]), "+r"(d[3])
        : "r"(a[0]), "r"(a[1]), "r"(a[2]), "r"(a[3]), "r"(b[0]), "r"(b[1]));
}

// quantize one float to (h,l) s8 pair given cs = topscale: t = v*cs; h=rni(t); l=rni(256(t-h))
__device__ __forceinline__ void quant2(float v, float cs, int& h, int& l){
    float t = v * cs;
    h = __float2int_rn(t);
    l = __float2int_rn(256.f * (t - (float)h));
    l = min(l, 127);            // edge +128 -> saturate
    l = max(l, -128);
}

// ================= static device scratch =================
__device__ __align__(16) float g_partialG[2u * NN * UN];   // 8 MB (2 k-split planes)
__device__ __align__(16) s8    g_w8hi[UN * NN];            // 1 MB  w_gcn^T s8 hi [256][4096]
__device__ __align__(16) s8    g_w8lo[UN * NN];            // 1 MB
__device__ __align__(16) u16   g_Gt_hi[UN * NN];           // 2 MB  G^T fp16 hi
__device__ __align__(16) u16   g_Gt_lo[UN * NN];           // 2 MB
__device__ __align__(16) float g_partialX[8u * BT * UN];   // 4 MB
__device__ __align__(16) float g_X[BT * UN];               // 0.5 MB
__device__ __align__(16) u16   g_gw_hi[512 * 512];         // 512 KB gate weights
__device__ __align__(16) u16   g_gw_lo[512 * 512];         // 512 KB

// ================= SMEM geometry =================
// kernelA (s8): row stride 48 (32 data + 16 pad) — conflict-free (12g+tig mod 32 distinct)
#define A8_ROW   48
#define A8_AHI   0
#define A8_ALO   1536
#define A8_BHI   3072
#define A8_BLO   15360
#define A8_BUFST 27648
#define A8_SMEM  (2 * A8_BUFST)
// kernelB (fp16): unchanged from R9
#define ROWB 80
#define B_OFF_AHI 0
#define B_OFF_ALO 5120
#define B_OFF_BHI 10240
#define B_OFF_BLO 20480
#define B_BUFST   30720
#define B_SMEMSZ  (2 * B_BUFST)
// kernelC (fp16): unchanged from R9
#define C_OFF_AHI 0
#define C_OFF_ALO 2560
#define C_OFF_BHI 5120
#define C_OFF_BLO 15360
#define C_BUFST   25600
#define C_SMEMSZ  (2 * C_BUFST)

// =====================================================================
// kPrepW8: w_gcn [4096][256] -> g_w8hi/lo [256][4096] s8 (transpose + quantize)
// =====================================================================
__global__ void kPrepW8(const float* __restrict__ wgcn)
{
    __shared__ float tile[32][33];
    const int k0 = blockIdx.x * 32, n0 = blockIdx.y * 32;
    const int c = threadIdx.x & 31, r = threadIdx.x >> 5;
    const float cs = 127.f / WCLIP;
#pragma unroll
    for (int i = 0; i < 4; i++)
        tile[r + 8*i][c] = wgcn[(size_t)(k0 + r + 8*i) * UN + n0 + c];
    __syncthreads();
#pragma unroll
    for (int i = 0; i < 4; i++){
        float v = tile[c][r + 8*i];
        float t = v * cs;
        int h = __float2int_rn(t);
        h = min(127, max(-127, h));
        int l = __float2int_rn(256.f * (t - (float)h));
        l = min(127, max(-128, l));
        size_t o = (size_t)(n0 + r + 8*i) * NN + k0 + c;
        g_w8hi[o] = (s8)h;
        g_w8lo[o] = (s8)l;
    }
}

// =====================================================================
// kPrepGates: wz/uz/wh/uh -> g_gw_hi/lo [512][512] (unchanged)
// =====================================================================
__global__ void kPrepGates(const float* __restrict__ wz, const float* __restrict__ uz,
                           const float* __restrict__ wh, const float* __restrict__ uh)
{
    __shared__ float tile[32][33];
    const int k0 = blockIdx.x * 32, n0 = blockIdx.y * 32;
    const int c = threadIdx.x & 31, r = threadIdx.x >> 5;
#pragma unroll
    for (int i = 0; i < 4; i++){
        int kk = k0 + r + 8*i;
        int nn = n0 + c;
        const float* src = (kk < 256) ? ((nn < 256) ? wz : wh) : ((nn < 256) ? uz : uh);
        tile[r + 8*i][c] = src[(size_t)(kk & 255) * UN + (nn & 255)];
    }
    __syncthreads();
#pragma unroll
    for (int i = 0; i < 4; i++){
        float v = tile[c][r + 8*i];
        size_t o = (size_t)(n0 + r + 8*i) * 512 + k0 + c;
        split1h(v, g_gw_hi[o], g_gw_lo[o]);
    }
}

// =====================================================================
// kernelA: s8 fixed-point 3-term GEMM.
// partialG[ks] = adj_mix[m0:m0+32, ks*2048:+2048] @ w_gcn
// grid (128 m-tiles, 2 ksplit) = 256 CTAs, 256 threads, occ 2, 64 stages BK=32
// =====================================================================
#define KA_NST 64

__global__ __launch_bounds__(256, 2) void kernelA(const float* __restrict__ adj,
                                                  const float* __restrict__ wap)
{
    extern __shared__ __align__(16) char smem[];
    const uint32_t sb = smem_u32(smem);
    const int tid = threadIdx.x, wid = tid >> 5, lane = tid & 31;
    const int g = lane >> 2, tig = lane & 3;
    const int m0 = blockIdx.x * 32;
    const int kbase = blockIdx.y * 2048;
    const float w0 = wap[0], w1 = wap[1], w2 = wap[2];
    const float s = w0 + w1 + w2;
    const float csA = 127.f / s;
    const size_t GS = (size_t)NN * NN;

    const int arow = tid >> 3;     // 0..31
    const int aq   = tid & 7;      // 4-byte col group

    int accH[8][4], accM[8][4];
#pragma unroll
    for (int b = 0; b < 8; b++)
#pragma unroll
        for (int c = 0; c < 4; c++){ accH[b][c] = 0; accM[b][c] = 0; }

    float4 ra[3];

    auto issueB = [&](int t, int b){
#pragma unroll
        for (int j = 0; j < 4; j++){
            int f = j*256 + tid;
            int row = f >> 2, c = f & 3;
            int plane = c >> 1, half = c & 1;
            uint32_t daddr = sb + b*A8_BUFST + (plane ? A8_BLO : A8_BHI) + row*A8_ROW + half*16;
            const s8* src = (plane ? g_w8lo : g_w8hi) + (size_t)row * NN + kbase + t*32 + half*16;
            cpasync16(daddr, src);
        }
        CP_COMMIT;
    };
    auto loadA = [&](int t){
        const float* p = adj + (size_t)(m0 + arow) * NN + kbase + t*32 + aq*4;
        ra[0] = __ldg((const float4*)p);
        ra[1] = __ldg((const float4*)(p + GS));
        ra[2] = __ldg((const float4*)(p + 2*GS));
    };
    auto storeA = [&](int b){
        char* base = smem + b*A8_BUFST;
        float v0 = fmaf(w0, ra[0].x, fmaf(w1, ra[1].x, w2*ra[2].x));
        float v1 = fmaf(w0, ra[0].y, fmaf(w1, ra[1].y, w2*ra[2].y));
        float v2 = fmaf(w0, ra[0].z, fmaf(w1, ra[1].z, w2*ra[2].z));
        float v3 = fmaf(w0, ra[0].w, fmaf(w1, ra[1].w, w2*ra[2].w));
        int h0,l0,h1,l1,h2,l2,h3,l3;
        quant2(v0, csA, h0, l0);
        quant2(v1, csA, h1, l1);
        quant2(v2, csA, h2, l2);
        quant2(v3, csA, h3, l3);
        uint32_t Hw = (h0 & 255) | ((h1 & 255) << 8) | ((h2 & 255) << 16) | ((h3 & 255) << 24);
        uint32_t Lw = (l0 & 255) | ((l1 & 255) << 8) | ((l2 & 255) << 16) | ((l3 & 255) << 24);
        *(uint32_t*)(base + A8_AHI + arow*A8_ROW + aq*4) = Hw;
        *(uint32_t*)(base + A8_ALO + arow*A8_ROW + aq*4) = Lw;
    };

    issueB(0, 0);
    loadA(0); storeA(0);
    CP_WAIT0; __syncthreads();

    const int amBase = (wid & 1) * 16;
    const int bnBase = (wid >> 1) * 64;

    for (int t = 0; t < KA_NST; t++){
        const int b = t & 1;
        if (t + 1 < KA_NST){ issueB(t + 1, b ^ 1); loadA(t + 1); }

        const char* buf = smem + b*A8_BUFST;
        const int ko = tig * 4;
        const char* pa = buf + A8_AHI + (amBase + g) * A8_ROW + ko;
        uint32_t ah[4] = { *(const uint32_t*)pa,        *(const uint32_t*)(pa + 8*A8_ROW),
                           *(const uint32_t*)(pa + 16), *(const uint32_t*)(pa + 8*A8_ROW + 16) };
        const char* ql = buf + A8_ALO + (amBase + g) * A8_ROW + ko;
        uint32_t al[4] = { *(const uint32_t*)ql,        *(const uint32_t*)(ql + 8*A8_ROW),
                           *(const uint32_t*)(ql + 16), *(const uint32_t*)(ql + 8*A8_ROW + 16) };
#pragma unroll
        for (int ni = 0; ni < 8; ni++){
            const char* pb = buf + A8_BHI + (bnBase + g + ni*8) * A8_ROW + ko;
            uint32_t bh[2] = { *(const uint32_t*)pb, *(const uint32_t*)(pb + 16) };
            const char* qb = buf + A8_BLO + (bnBase + g + ni*8) * A8_ROW + ko;
            uint32_t bl[2] = { *(const uint32_t*)qb, *(const uint32_t*)(qb + 16) };
            mma16832s8(accH[ni], ah, bh);
            mma16832s8(accM[ni], ah, bl);
            mma16832s8(accM[ni], al, bh);
        }

        if (t + 1 < KA_NST) storeA(b ^ 1);
        CP_WAIT0; __syncthreads();
    }

    // epilogue: combine planes -> float
    const float inv = s * WCLIP / (32512.f * 32512.f);
    float* dst = g_partialG + (size_t)blockIdx.y * (NN * UN);
    const int m = m0 + amBase + g;
#pragma unroll
    for (int ni = 0; ni < 8; ni++){
        int n = bnBase + ni*8 + tig*2;
        float d0 = fmaf(65536.f, (float)accH[ni][0], 256.f * (float)accM[ni][0]) * inv;
        float d1 = fmaf(65536.f, (float)accH[ni][1], 256.f * (float)accM[ni][1]) * inv;
        float d2 = fmaf(65536.f, (float)accH[ni][2], 256.f * (float)accM[ni][2]) * inv;
        float d3 = fmaf(65536.f, (float)accH[ni][3], 256.f * (float)accM[ni][3]) * inv;
        *(float2*)(dst + (size_t)m * UN + n)       = make_float2(d0, d1);
        *(float2*)(dst + (size_t)(m + 8) * UN + n) = make_float2(d2, d3);
    }
}

// =====================================================================
// kReduceGT: G = sum of 2 partials; transpose + fp16 split -> g_Gt_hi/lo
// vectorized float4 loads; grid (128, 8), 256 threads
// =====================================================================
__global__ void kReduceGT()
{
    __shared__ float tile[32][33];
    const int k0 = blockIdx.x * 32, n0 = blockIdx.y * 32;
    const int tid = threadIdx.x;
    {
        const int r = tid >> 3, q = tid & 7;           // row 0..31, float4-col 0..7
        size_t o = (size_t)(k0 + r) * UN + n0 + q*4;
        float4 a = *(const float4*)(g_partialG + o);
        float4 b = *(const float4*)(g_partialG + (size_t)NN*UN + o);
        tile[r][q*4+0] = a.x + b.x;
        tile[r][q*4+1] = a.y + b.y;
        tile[r][q*4+2] = a.z + b.z;
        tile[r][q*4+3] = a.w + b.w;
    }
    __syncthreads();
    {
        const int nr = tid >> 3, kq = tid & 7;         // n' 0..31, k-quad 0..7
        u16 hh[4], ll[4];
#pragma unroll
        for (int j = 0; j < 4; j++)
            split1h(tile[kq*4+j][nr], hh[j], ll[j]);
        size_t o = (size_t)(n0 + nr) * NN + k0 + kq*4;
        *(uint2*)(g_Gt_hi + o) = *(uint2*)hh;
        *(uint2*)(g_Gt_lo + o) = *(uint2*)ll;
    }
}

// =====================================================================
// kernelB: partialX[ks] = inputs @ G  (fp16 3-term, unchanged from R9)
// grid (8 m, 2 n, 8 ksplit) = 128 CTAs
// =====================================================================
#define KB_NST 16

__global__ __launch_bounds__(256, 2) void kernelB(const float* __restrict__ inputs)
{
    extern __shared__ __align__(16) char smem[];
    const uint32_t sb = smem_u32(smem);
    const int tid = threadIdx.x, wid = tid >> 5, lane = tid & 31;
    const int g = lane >> 2, tig = lane & 3;
    const int m0 = blockIdx.x * 64, n0 = blockIdx.y * 128;
    const int kbase = blockIdx.z * 512;

    float acc[2][4][4];
#pragma unroll
    for (int a = 0; a < 2; a++)
#pragma unroll
        for (int b = 0; b < 4; b++)
#pragma unroll
            for (int c = 0; c < 4; c++) acc[a][b][c] = 0.f;

    float4 ra[2];

    auto issueB = [&](int t, int b){
#pragma unroll
        for (int j = 0; j < 2; j++){
            int f = j*256 + tid, row = f >> 2, c = f & 3;
            uint32_t daddr = sb + b*B_BUFST + row*ROWB + c*16;
            size_t go = (size_t)(n0 + row) * NN + kbase + t*32 + c*8;
            cpasync16(daddr + B_OFF_BHI, g_Gt_hi + go);
            cpasync16(daddr + B_OFF_BLO, g_Gt_lo + go);
        }
        CP_COMMIT;
    };
    auto loadA = [&](int t){
#pragma unroll
        for (int j = 0; j < 2; j++){
            int f = j*256 + tid, row = f >> 3, q = f & 7;
            ra[j] = __ldg((const float4*)(inputs + (size_t)(m0 + row) * NN + kbase + t*32 + q*4));
        }
    };
    auto storeA = [&](int b){
        char* base = smem + b*B_BUFST;
#pragma unroll
        for (int j = 0; j < 2; j++){
            int f = j*256 + tid, row = f >> 3, q = f & 7;
            uint32_t h0, l0, h1, l1;
            split2h(ra[j].x, ra[j].y, h0, l0);
            split2h(ra[j].z, ra[j].w, h1, l1);
            *(uint2*)(base + B_OFF_AHI + row*ROWB + q*8) = make_uint2(h0, h1);
            *(uint2*)(base + B_OFF_ALO + row*ROWB + q*8) = make_uint2(l0, l1);
        }
    };

    issueB(0, 0);
    loadA(0); storeA(0);
    CP_WAIT0; __syncthreads();

    const int am = (wid & 1) * 32 + g;
    const int bn = (wid >> 1) * 32 + g;

    for (int t = 0; t < KB_NST; t++){
        const int b = t & 1;
        if (t + 1 < KB_NST){ issueB(t + 1, b ^ 1); loadA(t + 1); }

        const char* buf = smem + b*B_BUFST;
#pragma unroll
        for (int s = 0; s < 2; s++){
            const int ko = s * 32 + tig * 4;
            uint32_t ah[2][4], al[2][4];
#pragma unroll
            for (int mi = 0; mi < 2; mi++){
                const char* pa = buf + B_OFF_AHI + (am + mi*16) * ROWB + ko;
                ah[mi][0] = *(const uint32_t*)pa;        ah[mi][1] = *(const uint32_t*)(pa + 8*ROWB);
                ah[mi][2] = *(const uint32_t*)(pa + 16); ah[mi][3] = *(const uint32_t*)(pa + 8*ROWB + 16);
                const char* ql = buf + B_OFF_ALO + (am + mi*16) * ROWB + ko;
                al[mi][0] = *(const uint32_t*)ql;        al[mi][1] = *(const uint32_t*)(ql + 8*ROWB);
                al[mi][2] = *(const uint32_t*)(ql + 16); al[mi][3] = *(const uint32_t*)(ql + 8*ROWB + 16);
            }
#pragma unroll
            for (int ni = 0; ni < 4; ni++){
                const char* pb = buf + B_OFF_BHI + (bn + ni*8) * ROWB + ko;
                uint32_t bh[2] = { *(const uint32_t*)pb, *(const uint32_t*)(pb + 16) };
                const char* qb = buf + B_OFF_BLO + (bn + ni*8) * ROWB + ko;
                uint32_t bl[2] = { *(const uint32_t*)qb, *(const uint32_t*)(qb + 16) };
#pragma unroll
                for (int mi = 0; mi < 2; mi++){
                    mma16816h(acc[mi][ni], ah[mi], bh);
                    mma16816h(acc[mi][ni], ah[mi], bl);
                    mma16816h(acc[mi][ni], al[mi], bh);
                }
            }
        }

        if (t + 1 < KB_NST) storeA(b ^ 1);
        CP_WAIT0; __syncthreads();
    }

    float* dst = g_partialX + (size_t)blockIdx.z * (BT * UN);
#pragma unroll
    for (int mi = 0; mi < 2; mi++){
        int m = m0 + am + mi*16;
#pragma unroll
        for (int ni = 0; ni < 4; ni++){
            int n = n0 + bn - g + ni*8 + tig*2;
            *(float2*)(dst + (size_t)m * UN + n)       = make_float2(acc[mi][ni][0], acc[mi][ni][1]);
            *(float2*)(dst + (size_t)(m + 8) * UN + n) = make_float2(acc[mi][ni][2], acc[mi][ni][3]);
        }
    }
}

// =====================================================================
// kReduceX: X = relu(sum of 8 partials)
// =====================================================================
__global__ void kReduceX()
{
    int i = blockIdx.x * blockDim.x + threadIdx.x;
    const float4* p = (const float4*)g_partialX;
    float4 s = p[i];
#pragma unroll
    for (int s8i = 1; s8i < 8; s8i++){
        float4 t = p[(size_t)s8i * (BT*UN/4) + i];
        s.x += t.x; s.y += t.y; s.z += t.z; s.w += t.w;
    }
    s.x = fmaxf(s.x, 0.f); s.y = fmaxf(s.y, 0.f);
    s.z = fmaxf(s.z, 0.f); s.w = fmaxf(s.w, 0.f);
    ((float4*)g_X)[i] = s;
}

// =====================================================================
// kernelC: fused GRU gate GEMM + epilogue (unchanged from R9, grid (16,4))
// =====================================================================
#define KC_NST 16

__global__ __launch_bounds__(256, 2) void kernelC(const float* __restrict__ state,
    const float* __restrict__ bz, const float* __restrict__ bh,
    float* __restrict__ out)
{
    extern __shared__ __align__(16) char smem[];
    const uint32_t sb = smem_u32(smem);
    const int tid = threadIdx.x, wid = tid >> 5, lane = tid & 31;
    const int g = lane >> 2, tig = lane & 3;
    const int m0 = blockIdx.x * 32;
    const int n0 = blockIdx.y * 64;

    float accz[2][4], acch[2][4];
#pragma unroll
    for (int a = 0; a < 2; a++)
#pragma unroll
        for (int c = 0; c < 4; c++){ accz[a][c] = 0.f; acch[a][c] = 0.f; }

    const int arow = tid >> 3;
    const int aq   = tid & 7;
    float4 ra;

    auto issueB = [&](int t, int b){
#pragma unroll
        for (int j = 0; j < 2; j++){
            int f = j*256 + tid, r = f >> 2, c = f & 3;
            int nprime = (r < 64) ? (n0 + r) : (256 + n0 + (r - 64));
            uint32_t daddr = sb + b*C_BUFST + r*ROWB + c*16;
            size_t go = (size_t)nprime * 512 + t*32 + c*8;
            cpasync16(daddr + C_OFF_BHI, g_gw_hi + go);
            cpasync16(daddr + C_OFF_BLO, g_gw_lo + go);
        }
        CP_COMMIT;
    };
    auto loadA = [&](int t){
        int kp = t*32 + aq*4;
        if (kp < 256)
            ra = *(const float4*)(g_X + (size_t)(m0 + arow) * UN + kp);
        else
            ra = __ldg((const float4*)(state + (size_t)(m0 + arow) * UN + (kp - 256)));
    };
    auto storeA = [&](int b){
        char* base = smem + b*C_BUFST;
        uint32_t h0, l0, h1, l1;
        split2h(ra.x, ra.y, h0, l0);
        split2h(ra.z, ra.w, h1, l1);
        *(uint2*)(base + C_OFF_AHI + arow*ROWB + aq*8) = make_uint2(h0, h1);
        *(uint2*)(base + C_OFF_ALO + arow*ROWB + aq*8) = make_uint2(l0, l1);
    };

    issueB(0, 0);
    loadA(0); storeA(0);
    CP_WAIT0; __syncthreads();

    const int am = (wid & 1) * 16 + g;
    const int bn = (wid >> 1) * 16;

    for (int t = 0; t < KC_NST; t++){
        const int b = t & 1;
        if (t + 1 < KC_NST){ issueB(t + 1, b ^ 1); loadA(t + 1); }

        const char* buf = smem + b*C_BUFST;
#pragma unroll
        for (int s = 0; s < 2; s++){
            const int ko = s * 32 + tig * 4;
            const char* pa = buf + C_OFF_AHI + am * ROWB + ko;
            uint32_t ah[4] = { *(const uint32_t*)pa,        *(const uint32_t*)(pa + 8*ROWB),
                               *(const uint32_t*)(pa + 16), *(const uint32_t*)(pa + 8*ROWB + 16) };
            const char* ql = buf + C_OFF_ALO + am * ROWB + ko;
            uint32_t al[4] = { *(const uint32_t*)ql,        *(const uint32_t*)(ql + 8*ROWB),
                               *(const uint32_t*)(ql + 16), *(const uint32_t*)(ql + 8*ROWB + 16) };
#pragma unroll
            for (int ni = 0; ni < 2; ni++){
                const char* pb = buf + C_OFF_BHI + (bn + g + ni*8) * ROWB + ko;
                uint32_t bhz[2] = { *(const uint32_t*)pb, *(const uint32_t*)(pb + 16) };
                const char* qb = buf + C_OFF_BLO + (bn + g + ni*8) * ROWB + ko;
                uint32_t blz[2] = { *(const uint32_t*)qb, *(const uint32_t*)(qb + 16) };
                mma16816h(accz[ni], ah, bhz);
                mma16816h(accz[ni], ah, blz);
                mma16816h(accz[ni], al, bhz);
                const char* ph = buf + C_OFF_BHI + (64 + bn + g + ni*8) * ROWB + ko;
                uint32_t bhh[2] = { *(const uint32_t*)ph, *(const uint32_t*)(ph + 16) };
                const char* qh = buf + C_OFF_BLO + (64 + bn + g + ni*8) * ROWB + ko;
                uint32_t blh[2] = { *(const uint32_t*)qh, *(const uint32_t*)(qh + 16) };
                mma16816h(acch[ni], ah, bhh);
                mma16816h(acch[ni], ah, blh);
                mma16816h(acch[ni], al, bhh);
            }
        }

        if (t + 1 < KC_NST) storeA(b ^ 1);
        CP_WAIT0; __syncthreads();
    }

#pragma unroll
    for (int ni = 0; ni < 2; ni++){
        int n = n0 + bn + ni*8 + tig*2;
        float2 bzv = *(const float2*)(bz + n);
        float2 bhv = *(const float2*)(bh + n);
#pragma unroll
        for (int half = 0; half < 2; half++){
            int m = m0 + am + half*8;
            float pz0 = accz[ni][half*2+0] + bzv.x;
            float pz1 = accz[ni][half*2+1] + bzv.y;
            float ph0 = acch[ni][half*2+0] + bhv.x;
            float ph1 = acch[ni][half*2+1] + bhv.y;
            float2 sv = *(const float2*)(state + (size_t)m * UN + n);
            float z0 = 1.0f / (1.0f + expf(-pz0));
            float z1 = 1.0f / (1.0f + expf(-pz1));
            float h0 = tanhf(ph0);
            float h1 = tanhf(ph1);
            float o0 = sv.x + z0 * (h0 - sv.x);
            float o1 = sv.y + z1 * (h1 - sv.y);
            *(float2*)(out + (size_t)m * UN + n) = make_float2(o0, o1);
        }
    }
}

// =====================================================================
extern "C" void kernel_launch(void* const* d_in, const int* in_sizes, int n_in,
                              void* d_out, int out_size)
{
    const float* inputs = (const float*)d_in[0];
    const float* state  = (const float*)d_in[1];
    const float* adj    = (const float*)d_in[2];
    const float* wa     = (const float*)d_in[3];
    const float* wgcn   = (const float*)d_in[4];
    const float* wz     = (const float*)d_in[5];
    const float* uz     = (const float*)d_in[6];
    const float* bz     = (const float*)d_in[7];
    const float* wh     = (const float*)d_in[8];
    const float* uh     = (const float*)d_in[9];
    const float* bh     = (const float*)d_in[10];
    float* out = (float*)d_out;

    cudaFuncSetAttribute(kernelA, cudaFuncAttributeMaxDynamicSharedMemorySize, A8_SMEM);
    cudaFuncSetAttribute(kernelB, cudaFuncAttributeMaxDynamicSharedMemorySize, B_SMEMSZ);
    cudaFuncSetAttribute(kernelC, cudaFuncAttributeMaxDynamicSharedMemorySize, C_SMEMSZ);

    kPrepW8<<<dim3(NN/32, UN/32), 256>>>(wgcn);
    kPrepGates<<<dim3(16, 16), 256>>>(wz, uz, wh, uh);
    kernelA<<<dim3(128, 2), 256, A8_SMEM>>>(adj, wa);
    kReduceGT<<<dim3(NN/32, UN/32), 256>>>();
    kernelB<<<dim3(8, 2, 8), 256, B_SMEMSZ>>>(inputs);
    kReduceX<<<128, 256>>>();
    kernelC<<<dim3(16, 4), 256, C_SMEMSZ>>>(state, bz, bh, out);
}

// round 11
// speedup vs baseline: 2.3272x; 2.3272x over previous
#include <cuda_runtime.h>
#include <math.h>
#include <stdint.h>

typedef unsigned long long ull;
typedef unsigned short u16;

#define NN 4096
#define UN 256
#define BT 512

// ================= helpers =================
__device__ __forceinline__ uint32_t smem_u32(const void* p){
    uint32_t a;
    asm("{ .reg .u64 t; cvta.to.shared.u64 t, %1; cvt.u32.u64 %0, t; }" : "=r"(a) : "l"(p));
    return a;
}
__device__ __forceinline__ void cpasync16(uint32_t daddr, const void* gptr){
    asm volatile("cp.async.cg.shared.global [%0], [%1], 16;" :: "r"(daddr), "l"(gptr));
}
#define CP_COMMIT asm volatile("cp.async.commit_group;" ::: "memory")
#define CP_WAIT0  asm volatile("cp.async.wait_group 0;" ::: "memory")

// fp16 hi/lo split helpers
__device__ __forceinline__ void split2h(float v0, float v1, uint32_t& hp, uint32_t& lp){
    u16 h0, h1, l0, l1;
    asm("cvt.rn.f16.f32 %0, %1;" : "=h"(h0) : "f"(v0));
    asm("cvt.rn.f16.f32 %0, %1;" : "=h"(h1) : "f"(v1));
    float f0, f1;
    asm("cvt.f32.f16 %0, %1;" : "=f"(f0) : "h"(h0));
    asm("cvt.f32.f16 %0, %1;" : "=f"(f1) : "h"(h1));
    asm("cvt.rn.f16.f32 %0, %1;" : "=h"(l0) : "f"(v0 - f0));
    asm("cvt.rn.f16.f32 %0, %1;" : "=h"(l1) : "f"(v1 - f1));
    asm("mov.b32 %0, {%1, %2};" : "=r"(hp) : "h"(h0), "h"(h1));
    asm("mov.b32 %0, {%1, %2};" : "=r"(lp) : "h"(l0), "h"(l1));
}
__device__ __forceinline__ void split1h(float v, u16& h, u16& l){
    u16 hb, lb;
    asm("cvt.rn.f16.f32 %0, %1;" : "=h"(hb) : "f"(v));
    float hf;
    asm("cvt.f32.f16 %0, %1;" : "=f"(hf) : "h"(hb));
    asm("cvt.rn.f16.f32 %0, %1;" : "=h"(lb) : "f"(v - hf));
    h = hb; l = lb;
}
__device__ __forceinline__ u16 cvt1h(float v){
    u16 hb;
    asm("cvt.rn.f16.f32 %0, %1;" : "=h"(hb) : "f"(v));
    return hb;
}

__device__ __forceinline__ void mma16816h(float* d, const uint32_t* a, const uint32_t* b){
    asm volatile("mma.sync.aligned.m16n8k16.row.col.f32.f16.f16.f32 "
        "{%0,%1,%2,%3}, {%4,%5,%6,%7}, {%8,%9}, {%0,%1,%2,%3};"
        : "+f"(d[0]), "+f"(d[1]), "+f"(d[2]), "+f"(d[3])
        : "r"(a[0]), "r"(a[1]), "r"(a[2]), "r"(a[3]), "r"(b[0]), "r"(b[1]));
}

// ================= static device scratch =================
__device__ __align__(16) float g_partialG[2u * NN * UN];   // 8 MB (2 ksplit planes)
__device__ __align__(16) u16   g_wth[UN * NN];             // 2 MB  w_gcn^T fp16 single-plane
__device__ __align__(16) u16   g_Gt_hi[UN * NN];           // 2 MB  G^T fp16 hi
__device__ __align__(16) u16   g_Gt_lo[UN * NN];           // 2 MB
__device__ __align__(16) float g_partialX[8u * BT * UN];   // 4 MB
__device__ __align__(16) float g_X[BT * UN];               // 0.5 MB
__device__ __align__(16) u16   g_gw_hi[512 * 512];         // 512 KB gate weights
__device__ __align__(16) u16   g_gw_lo[512 * 512];         // 512 KB

// ================= SMEM geometry =================
#define ROWB 80
// kernelA (R5 fat-tile): [A_hi 10240][A_lo 10240][B 10240]
#define A_OFF_AHI 0
#define A_OFF_ALO 10240
#define A_OFF_B   20480
#define A_BUFST   30720
#define A_SMEMSZ  (2 * A_BUFST)
// kernelB: M=64, N=128
#define B_OFF_AHI 0
#define B_OFF_ALO 5120
#define B_OFF_BHI 10240
#define B_OFF_BLO 20480
#define B_BUFST   30720
#define B_SMEMSZ  (2 * B_BUFST)
// kernelC: M=32, N=128 (64 z + 64 h)
#define C_OFF_AHI 0
#define C_OFF_ALO 2560
#define C_OFF_BHI 5120
#define C_OFF_BLO 15360
#define C_BUFST   25600
#define C_SMEMSZ  (2 * C_BUFST)

// =====================================================================
// kPrepW: w_gcn [4096][256] -> g_wth [256][4096] fp16 (transpose)
// =====================================================================
__global__ void kPrepW(const float* __restrict__ wgcn)
{
    __shared__ float tile[32][33];
    const int k0 = blockIdx.x * 32, n0 = blockIdx.y * 32;
    const int c = threadIdx.x & 31, r = threadIdx.x >> 5;
#pragma unroll
    for (int i = 0; i < 4; i++)
        tile[r + 8*i][c] = wgcn[(size_t)(k0 + r + 8*i) * UN + n0 + c];
    __syncthreads();
#pragma unroll
    for (int i = 0; i < 4; i++){
        size_t o = (size_t)(n0 + r + 8*i) * NN + k0 + c;
        g_wth[o] = cvt1h(tile[c][r + 8*i]);
    }
}

// =====================================================================
// kPrepGates: wz/uz/wh/uh -> g_gw_hi/lo [512 n'][512 k'] (transpose+split)
// =====================================================================
__global__ void kPrepGates(const float* __restrict__ wz, const float* __restrict__ uz,
                           const float* __restrict__ wh, const float* __restrict__ uh)
{
    __shared__ float tile[32][33];
    const int k0 = blockIdx.x * 32, n0 = blockIdx.y * 32;
    const int c = threadIdx.x & 31, r = threadIdx.x >> 5;
#pragma unroll
    for (int i = 0; i < 4; i++){
        int kk = k0 + r + 8*i;
        int nn = n0 + c;
        const float* src = (kk < 256) ? ((nn < 256) ? wz : wh) : ((nn < 256) ? uz : uh);
        tile[r + 8*i][c] = src[(size_t)(kk & 255) * UN + (nn & 255)];
    }
    __syncthreads();
#pragma unroll
    for (int i = 0; i < 4; i++){
        float v = tile[c][r + 8*i];
        size_t o = (size_t)(n0 + r + 8*i) * 512 + k0 + c;
        split1h(v, g_gw_hi[o], g_gw_lo[o]);
    }
}

// =====================================================================
// kernelA (R5 verbatim): partialG[ks] = adj_mix[m0:m0+128, ks*2048:+2048] @ w_gcn
// fp16 2-term; grid (32 m, 2 n, 2 ksplit), 256 threads, 64 stages BK=32.
// Per warp (2m x 4n): M64 x N32.
// =====================================================================
#define KA_NST 64     // 2048 / 32

__global__ __launch_bounds__(256, 1) void kernelA(const float* __restrict__ adj,
                                                  const float* __restrict__ wap)
{
    extern __shared__ __align__(16) char smem[];
    const uint32_t sb = smem_u32(smem);
    const int tid = threadIdx.x, wid = tid >> 5, lane = tid & 31;
    const int g = lane >> 2, tig = lane & 3;
    const int m0 = blockIdx.x * 128, n0 = blockIdx.y * 128;
    const int kbase = blockIdx.z * 2048;
    const float w0 = wap[0], w1 = wap[1], w2 = wap[2];
    const size_t GS = (size_t)NN * NN;

    float acc[4][4][4];
#pragma unroll
    for (int a = 0; a < 4; a++)
#pragma unroll
        for (int b = 0; b < 4; b++)
#pragma unroll
            for (int c = 0; c < 4; c++) acc[a][b][c] = 0.f;

    float4 ra[4][3];

    auto issueB = [&](int t, int b){
#pragma unroll
        for (int j = 0; j < 2; j++){
            int f = j*256 + tid, row = f >> 2, c = f & 3;
            uint32_t daddr = sb + b*A_BUFST + A_OFF_B + row*ROWB + c*16;
            size_t go = (size_t)(n0 + row) * NN + kbase + t*32 + c*8;
            cpasync16(daddr, g_wth + go);
        }
        CP_COMMIT;
    };
    auto loadA = [&](int t){
#pragma unroll
        for (int j = 0; j < 4; j++){
            int f = j*256 + tid, row = f >> 3, q = f & 7;
            const float* p = adj + (size_t)(m0 + row) * NN + kbase + t*32 + q*4;
            ra[j][0] = __ldg((const float4*)p);
            ra[j][1] = __ldg((const float4*)(p + GS));
            ra[j][2] = __ldg((const float4*)(p + 2*GS));
        }
    };
    auto storeA = [&](int b){
        char* base = smem + b*A_BUFST;
#pragma unroll
        for (int j = 0; j < 4; j++){
            int f = j*256 + tid, row = f >> 3, q = f & 7;
            float vx = fmaf(w0, ra[j][0].x, fmaf(w1, ra[j][1].x, w2*ra[j][2].x));
            float vy = fmaf(w0, ra[j][0].y, fmaf(w1, ra[j][1].y, w2*ra[j][2].y));
            float vz = fmaf(w0, ra[j][0].z, fmaf(w1, ra[j][1].z, w2*ra[j][2].z));
            float vw = fmaf(w0, ra[j][0].w, fmaf(w1, ra[j][1].w, w2*ra[j][2].w));
            uint32_t h0, l0, h1, l1;
            split2h(vx, vy, h0, l0);
            split2h(vz, vw, h1, l1);
            *(uint2*)(base + A_OFF_AHI + row*ROWB + q*8) = make_uint2(h0, h1);
            *(uint2*)(base + A_OFF_ALO + row*ROWB + q*8) = make_uint2(l0, l1);
        }
    };

    issueB(0, 0);
    loadA(0); storeA(0);
    CP_WAIT0; __syncthreads();

    const int am = (wid & 1) * 64 + g;
    const int bn = (wid >> 1) * 32 + g;

    for (int t = 0; t < KA_NST; t++){
        const int b = t & 1;
        if (t + 1 < KA_NST){ issueB(t + 1, b ^ 1); loadA(t + 1); }

        const char* buf = smem + b*A_BUFST;
#pragma unroll
        for (int s = 0; s < 2; s++){
            const int ko = s * 32 + tig * 4;
            uint32_t bh[4][2];
#pragma unroll
            for (int ni = 0; ni < 4; ni++){
                const char* p = buf + A_OFF_B + (bn + ni*8) * ROWB + ko;
                bh[ni][0] = *(const uint32_t*)p;
                bh[ni][1] = *(const uint32_t*)(p + 16);
            }
#pragma unroll
            for (int mi = 0; mi < 4; mi++){
                const char* p = buf + A_OFF_AHI + (am + mi*16) * ROWB + ko;
                uint32_t ah[4] = { *(const uint32_t*)p,        *(const uint32_t*)(p + 8*ROWB),
                                   *(const uint32_t*)(p + 16), *(const uint32_t*)(p + 8*ROWB + 16) };
                const char* q = buf + A_OFF_ALO + (am + mi*16) * ROWB + ko;
                uint32_t al[4] = { *(const uint32_t*)q,        *(const uint32_t*)(q + 8*ROWB),
                                   *(const uint32_t*)(q + 16), *(const uint32_t*)(q + 8*ROWB + 16) };
#pragma unroll
                for (int ni = 0; ni < 4; ni++){
                    mma16816h(acc[mi][ni], ah, bh[ni]);
                    mma16816h(acc[mi][ni], al, bh[ni]);
                }
            }
        }

        if (t + 1 < KA_NST) storeA(b ^ 1);
        CP_WAIT0; __syncthreads();
    }

    float* dst = g_partialG + (size_t)blockIdx.z * (NN * UN);
#pragma unroll
    for (int mi = 0; mi < 4; mi++){
#pragma unroll
        for (int ni = 0; ni < 4; ni++){
            int m = m0 + (wid & 1)*64 + mi*16 + g;
            int n = n0 + (wid >> 1)*32 + ni*8 + tig*2;
            *(float2*)(dst + (size_t)m * UN + n)       = make_float2(acc[mi][ni][0], acc[mi][ni][1]);
            *(float2*)(dst + (size_t)(m + 8) * UN + n) = make_float2(acc[mi][ni][2], acc[mi][ni][3]);
        }
    }
}

// =====================================================================
// kReduceGT: G = sum of 2 partials; transpose + fp16 split (vectorized)
// grid (128, 8), 256 threads
// =====================================================================
__global__ void kReduceGT()
{
    __shared__ float tile[32][33];
    const int k0 = blockIdx.x * 32, n0 = blockIdx.y * 32;
    const int tid = threadIdx.x;
    {
        const int r = tid >> 3, q = tid & 7;
        size_t o = (size_t)(k0 + r) * UN + n0 + q*4;
        float4 a = *(const float4*)(g_partialG + o);
        float4 b = *(const float4*)(g_partialG + (size_t)NN*UN + o);
        tile[r][q*4+0] = a.x + b.x;
        tile[r][q*4+1] = a.y + b.y;
        tile[r][q*4+2] = a.z + b.z;
        tile[r][q*4+3] = a.w + b.w;
    }
    __syncthreads();
    {
        const int nr = tid >> 3, kq = tid & 7;
        u16 hh[4], ll[4];
#pragma unroll
        for (int j = 0; j < 4; j++)
            split1h(tile[kq*4+j][nr], hh[j], ll[j]);
        size_t o = (size_t)(n0 + nr) * NN + k0 + kq*4;
        *(uint2*)(g_Gt_hi + o) = *(uint2*)hh;
        *(uint2*)(g_Gt_lo + o) = *(uint2*)ll;
    }
}

// =====================================================================
// kernelB: partialX[ks] = inputs @ G  (fp16 3-term, R9 fat-tile)
// grid (8 m, 2 n, 8 ksplit) = 128 CTAs
// =====================================================================
#define KB_NST 16

__global__ __launch_bounds__(256, 2) void kernelB(const float* __restrict__ inputs)
{
    extern __shared__ __align__(16) char smem[];
    const uint32_t sb = smem_u32(smem);
    const int tid = threadIdx.x, wid = tid >> 5, lane = tid & 31;
    const int g = lane >> 2, tig = lane & 3;
    const int m0 = blockIdx.x * 64, n0 = blockIdx.y * 128;
    const int kbase = blockIdx.z * 512;

    float acc[2][4][4];
#pragma unroll
    for (int a = 0; a < 2; a++)
#pragma unroll
        for (int b = 0; b < 4; b++)
#pragma unroll
            for (int c = 0; c < 4; c++) acc[a][b][c] = 0.f;

    float4 ra[2];

    auto issueB = [&](int t, int b){
#pragma unroll
        for (int j = 0; j < 2; j++){
            int f = j*256 + tid, row = f >> 2, c = f & 3;
            uint32_t daddr = sb + b*B_BUFST + row*ROWB + c*16;
            size_t go = (size_t)(n0 + row) * NN + kbase + t*32 + c*8;
            cpasync16(daddr + B_OFF_BHI, g_Gt_hi + go);
            cpasync16(daddr + B_OFF_BLO, g_Gt_lo + go);
        }
        CP_COMMIT;
    };
    auto loadA = [&](int t){
#pragma unroll
        for (int j = 0; j < 2; j++){
            int f = j*256 + tid, row = f >> 3, q = f & 7;
            ra[j] = __ldg((const float4*)(inputs + (size_t)(m0 + row) * NN + kbase + t*32 + q*4));
        }
    };
    auto storeA = [&](int b){
        char* base = smem + b*B_BUFST;
#pragma unroll
        for (int j = 0; j < 2; j++){
            int f = j*256 + tid, row = f >> 3, q = f & 7;
            uint32_t h0, l0, h1, l1;
            split2h(ra[j].x, ra[j].y, h0, l0);
            split2h(ra[j].z, ra[j].w, h1, l1);
            *(uint2*)(base + B_OFF_AHI + row*ROWB + q*8) = make_uint2(h0, h1);
            *(uint2*)(base + B_OFF_ALO + row*ROWB + q*8) = make_uint2(l0, l1);
        }
    };

    issueB(0, 0);
    loadA(0); storeA(0);
    CP_WAIT0; __syncthreads();

    const int am = (wid & 1) * 32 + g;
    const int bn = (wid >> 1) * 32 + g;

    for (int t = 0; t < KB_NST; t++){
        const int b = t & 1;
        if (t + 1 < KB_NST){ issueB(t + 1, b ^ 1); loadA(t + 1); }

        const char* buf = smem + b*B_BUFST;
#pragma unroll
        for (int s = 0; s < 2; s++){
            const int ko = s * 32 + tig * 4;
            uint32_t ah[2][4], al[2][4];
#pragma unroll
            for (int mi = 0; mi < 2; mi++){
                const char* pa = buf + B_OFF_AHI + (am + mi*16) * ROWB + ko;
                ah[mi][0] = *(const uint32_t*)pa;        ah[mi][1] = *(const uint32_t*)(pa + 8*ROWB);
                ah[mi][2] = *(const uint32_t*)(pa + 16); ah[mi][3] = *(const uint32_t*)(pa + 8*ROWB + 16);
                const char* ql = buf + B_OFF_ALO + (am + mi*16) * ROWB + ko;
                al[mi][0] = *(const uint32_t*)ql;        al[mi][1] = *(const uint32_t*)(ql + 8*ROWB);
                al[mi][2] = *(const uint32_t*)(ql + 16); al[mi][3] = *(const uint32_t*)(ql + 8*ROWB + 16);
            }
#pragma unroll
            for (int ni = 0; ni < 4; ni++){
                const char* pb = buf + B_OFF_BHI + (bn + ni*8) * ROWB + ko;
                uint32_t bh[2] = { *(const uint32_t*)pb, *(const uint32_t*)(pb + 16) };
                const char* qb = buf + B_OFF_BLO + (bn + ni*8) * ROWB + ko;
                uint32_t bl[2] = { *(const uint32_t*)qb, *(const uint32_t*)(qb + 16) };
#pragma unroll
                for (int mi = 0; mi < 2; mi++){
                    mma16816h(acc[mi][ni], ah[mi], bh);
                    mma16816h(acc[mi][ni], ah[mi], bl);
                    mma16816h(acc[mi][ni], al[mi], bh);
                }
            }
        }

        if (t + 1 < KB_NST) storeA(b ^ 1);
        CP_WAIT0; __syncthreads();
    }

    float* dst = g_partialX + (size_t)blockIdx.z * (BT * UN);
#pragma unroll
    for (int mi = 0; mi < 2; mi++){
        int m = m0 + am + mi*16;
#pragma unroll
        for (int ni = 0; ni < 4; ni++){
            int n = n0 + bn - g + ni*8 + tig*2;
            *(float2*)(dst + (size_t)m * UN + n)       = make_float2(acc[mi][ni][0], acc[mi][ni][1]);
            *(float2*)(dst + (size_t)(m + 8) * UN + n) = make_float2(acc[mi][ni][2], acc[mi][ni][3]);
        }
    }
}

// =====================================================================
// kReduceX: X = relu(sum of 8 partials)
// =====================================================================
__global__ void kReduceX()
{
    int i = blockIdx.x * blockDim.x + threadIdx.x;
    const float4* p = (const float4*)g_partialX;
    float4 s = p[i];
#pragma unroll
    for (int s8i = 1; s8i < 8; s8i++){
        float4 t = p[(size_t)s8i * (BT*UN/4) + i];
        s.x += t.x; s.y += t.y; s.z += t.z; s.w += t.w;
    }
    s.x = fmaxf(s.x, 0.f); s.y = fmaxf(s.y, 0.f);
    s.z = fmaxf(s.z, 0.f); s.w = fmaxf(s.w, 0.f);
    ((float4*)g_X)[i] = s;
}

// =====================================================================
// kernelC: fused GRU gate GEMM + epilogue (R9, grid (16,4))
// =====================================================================
#define KC_NST 16

__global__ __launch_bounds__(256, 2) void kernelC(const float* __restrict__ state,
    const float* __restrict__ bz, const float* __restrict__ bh,
    float* __restrict__ out)
{
    extern __shared__ __align__(16) char smem[];
    const uint32_t sb = smem_u32(smem);
    const int tid = threadIdx.x, wid = tid >> 5, lane = tid & 31;
    const int g = lane >> 2, tig = lane & 3;
    const int m0 = blockIdx.x * 32;
    const int n0 = blockIdx.y * 64;

    float accz[2][4], acch[2][4];
#pragma unroll
    for (int a = 0; a < 2; a++)
#pragma unroll
        for (int c = 0; c < 4; c++){ accz[a][c] = 0.f; acch[a][c] = 0.f; }

    const int arow = tid >> 3;
    const int aq   = tid & 7;
    float4 ra;

    auto issueB = [&](int t, int b){
#pragma unroll
        for (int j = 0; j < 2; j++){
            int f = j*256 + tid, r = f >> 2, c = f & 3;
            int nprime = (r < 64) ? (n0 + r) : (256 + n0 + (r - 64));
            uint32_t daddr = sb + b*C_BUFST + r*ROWB + c*16;
            size_t go = (size_t)nprime * 512 + t*32 + c*8;
            cpasync16(daddr + C_OFF_BHI, g_gw_hi + go);
            cpasync16(daddr + C_OFF_BLO, g_gw_lo + go);
        }
        CP_COMMIT;
    };
    auto loadA = [&](int t){
        int kp = t*32 + aq*4;
        if (kp < 256)
            ra = *(const float4*)(g_X + (size_t)(m0 + arow) * UN + kp);
        else
            ra = __ldg((const float4*)(state + (size_t)(m0 + arow) * UN + (kp - 256)));
    };
    auto storeA = [&](int b){
        char* base = smem + b*C_BUFST;
        uint32_t h0, l0, h1, l1;
        split2h(ra.x, ra.y, h0, l0);
        split2h(ra.z, ra.w, h1, l1);
        *(uint2*)(base + C_OFF_AHI + arow*ROWB + aq*8) = make_uint2(h0, h1);
        *(uint2*)(base + C_OFF_ALO + arow*ROWB + aq*8) = make_uint2(l0, l1);
    };

    issueB(0, 0);
    loadA(0); storeA(0);
    CP_WAIT0; __syncthreads();

    const int am = (wid & 1) * 16 + g;
    const int bn = (wid >> 1) * 16;

    for (int t = 0; t < KC_NST; t++){
        const int b = t & 1;
        if (t + 1 < KC_NST){ issueB(t + 1, b ^ 1); loadA(t + 1); }

        const char* buf = smem + b*C_BUFST;
#pragma unroll
        for (int s = 0; s < 2; s++){
            const int ko = s * 32 + tig * 4;
            const char* pa = buf + C_OFF_AHI + am * ROWB + ko;
            uint32_t ah[4] = { *(const uint32_t*)pa,        *(const uint32_t*)(pa + 8*ROWB),
                               *(const uint32_t*)(pa + 16), *(const uint32_t*)(pa + 8*ROWB + 16) };
            const char* ql = buf + C_OFF_ALO + am * ROWB + ko;
            uint32_t al[4] = { *(const uint32_t*)ql,        *(const uint32_t*)(ql + 8*ROWB),
                               *(const uint32_t*)(ql + 16), *(const uint32_t*)(ql + 8*ROWB + 16) };
#pragma unroll
            for (int ni = 0; ni < 2; ni++){
                const char* pb = buf + C_OFF_BHI + (bn + g + ni*8) * ROWB + ko;
                uint32_t bhz[2] = { *(const uint32_t*)pb, *(const uint32_t*)(pb + 16) };
                const char* qb = buf + C_OFF_BLO + (bn + g + ni*8) * ROWB + ko;
                uint32_t blz[2] = { *(const uint32_t*)qb, *(const uint32_t*)(qb + 16) };
                mma16816h(accz[ni], ah, bhz);
                mma16816h(accz[ni], ah, blz);
                mma16816h(accz[ni], al, bhz);
                const char* ph = buf + C_OFF_BHI + (64 + bn + g + ni*8) * ROWB + ko;
                uint32_t bhh[2] = { *(const uint32_t*)ph, *(const uint32_t*)(ph + 16) };
                const char* qh = buf + C_OFF_BLO + (64 + bn + g + ni*8) * ROWB + ko;
                uint32_t blh[2] = { *(const uint32_t*)qh, *(const uint32_t*)(qh + 16) };
                mma16816h(acch[ni], ah, bhh);
                mma16816h(acch[ni], ah, blh);
                mma16816h(acch[ni], al, bhh);
            }
        }

        if (t + 1 < KC_NST) storeA(b ^ 1);
        CP_WAIT0; __syncthreads();
    }

#pragma unroll
    for (int ni = 0; ni < 2; ni++){
        int n = n0 + bn + ni*8 + tig*2;
        float2 bzv = *(const float2*)(bz + n);
        float2 bhv = *(const float2*)(bh + n);
#pragma unroll
        for (int half = 0; half < 2; half++){
            int m = m0 + am + half*8;
            float pz0 = accz[ni][half*2+0] + bzv.x;
            float pz1 = accz[ni][half*2+1] + bzv.y;
            float ph0 = acch[ni][half*2+0] + bhv.x;
            float ph1 = acch[ni][half*2+1] + bhv.y;
            float2 sv = *(const float2*)(state + (size_t)m * UN + n);
            float z0 = 1.0f / (1.0f + expf(-pz0));
            float z1 = 1.0f / (1.0f + expf(-pz1));
            float h0 = tanhf(ph0);
            float h1 = tanhf(ph1);
            float o0 = sv.x + z0 * (h0 - sv.x);
            float o1 = sv.y + z1 * (h1 - sv.y);
            *(float2*)(out + (size_t)m * UN + n) = make_float2(o0, o1);
        }
    }
}

// =====================================================================
extern "C" void kernel_launch(void* const* d_in, const int* in_sizes, int n_in,
                              void* d_out, int out_size)
{
    const float* inputs = (const float*)d_in[0];
    const float* state  = (const float*)d_in[1];
    const float* adj    = (const float*)d_in[2];
    const float* wa     = (const float*)d_in[3];
    const float* wgcn   = (const float*)d_in[4];
    const float* wz     = (const float*)d_in[5];
    const float* uz     = (const float*)d_in[6];
    const float* bz     = (const float*)d_in[7];
    const float* wh     = (const float*)d_in[8];
    const float* uh     = (const float*)d_in[9];
    const float* bh     = (const float*)d_in[10];
    float* out = (float*)d_out;

    cudaFuncSetAttribute(kernelA, cudaFuncAttributeMaxDynamicSharedMemorySize, A_SMEMSZ);
    cudaFuncSetAttribute(kernelB, cudaFuncAttributeMaxDynamicSharedMemorySize, B_SMEMSZ);
    cudaFuncSetAttribute(kernelC, cudaFuncAttributeMaxDynamicSharedMemorySize, C_SMEMSZ);

    kPrepW<<<dim3(NN/32, UN/32), 256>>>(wgcn);
    kPrepGates<<<dim3(16, 16), 256>>>(wz, uz, wh, uh);
    kernelA<<<dim3(32, 2, 2), 256, A_SMEMSZ>>>(adj, wa);
    kReduceGT<<<dim3(NN/32, UN/32), 256>>>();
    kernelB<<<dim3(8, 2, 8), 256, B_SMEMSZ>>>(inputs);
    kReduceX<<<128, 256>>>();
    kernelC<<<dim3(16, 4), 256, C_SMEMSZ>>>(state, bz, bh, out);
}

// round 15
// speedup vs baseline: 2.3709x; 1.0188x over previous
#include <cuda_runtime.h>
#include <math.h>
#include <stdint.h>

typedef unsigned long long ull;
typedef unsigned short u16;

#define NN 4096
#define UN 256
#define BT 512

// ================= helpers =================
__device__ __forceinline__ uint32_t smem_u32(const void* p){
    uint32_t a;
    asm("{ .reg .u64 t; cvta.to.shared.u64 t, %1; cvt.u32.u64 %0, t; }" : "=r"(a) : "l"(p));
    return a;
}
__device__ __forceinline__ void cpasync16(uint32_t daddr, const void* gptr){
    asm volatile("cp.async.cg.shared.global [%0], [%1], 16;" :: "r"(daddr), "l"(gptr));
}
#define CP_COMMIT asm volatile("cp.async.commit_group;" ::: "memory")
#define CP_WAIT0  asm volatile("cp.async.wait_group 0;" ::: "memory")

// fp16 hi/lo split helpers
__device__ __forceinline__ void split2h(float v0, float v1, uint32_t& hp, uint32_t& lp){
    u16 h0, h1, l0, l1;
    asm("cvt.rn.f16.f32 %0, %1;" : "=h"(h0) : "f"(v0));
    asm("cvt.rn.f16.f32 %0, %1;" : "=h"(h1) : "f"(v1));
    float f0, f1;
    asm("cvt.f32.f16 %0, %1;" : "=f"(f0) : "h"(h0));
    asm("cvt.f32.f16 %0, %1;" : "=f"(f1) : "h"(h1));
    asm("cvt.rn.f16.f32 %0, %1;" : "=h"(l0) : "f"(v0 - f0));
    asm("cvt.rn.f16.f32 %0, %1;" : "=h"(l1) : "f"(v1 - f1));
    asm("mov.b32 %0, {%1, %2};" : "=r"(hp) : "h"(h0), "h"(h1));
    asm("mov.b32 %0, {%1, %2};" : "=r"(lp) : "h"(l0), "h"(l1));
}
__device__ __forceinline__ void split1h(float v, u16& h, u16& l){
    u16 hb, lb;
    asm("cvt.rn.f16.f32 %0, %1;" : "=h"(hb) : "f"(v));
    float hf;
    asm("cvt.f32.f16 %0, %1;" : "=f"(hf) : "h"(hb));
    asm("cvt.rn.f16.f32 %0, %1;" : "=h"(lb) : "f"(v - hf));
    h = hb; l = lb;
}
__device__ __forceinline__ u16 cvt1h(float v){
    u16 hb;
    asm("cvt.rn.f16.f32 %0, %1;" : "=h"(hb) : "f"(v));
    return hb;
}

__device__ __forceinline__ void mma16816h(float* d, const uint32_t* a, const uint32_t* b){
    asm volatile("mma.sync.aligned.m16n8k16.row.col.f32.f16.f16.f32 "
        "{%0,%1,%2,%3}, {%4,%5,%6,%7}, {%8,%9}, {%0,%1,%2,%3};"
        : "+f"(d[0]), "+f"(d[1]), "+f"(d[2]), "+f"(d[3])
        : "r"(a[0]), "r"(a[1]), "r"(a[2]), "r"(a[3]), "r"(b[0]), "r"(b[1]));
}

// ================= static device scratch =================
__device__ __align__(16) float g_partialG[2u * NN * UN];   // 8 MB
__device__ __align__(16) u16   g_wth[UN * NN];             // 2 MB  w_gcn^T fp16
__device__ __align__(16) u16   g_Gt_hi[UN * NN];           // 2 MB
__device__ __align__(16) u16   g_Gt_lo[UN * NN];           // 2 MB
__device__ __align__(16) float g_partialX[8u * BT * UN];   // 4 MB
__device__ __align__(16) u16   g_gw_hi[512 * 512];         // 512 KB
__device__ __align__(16) u16   g_gw_lo[512 * 512];         // 512 KB

// ================= SMEM geometry =================
// kernelA: BK=64, ROWB=144 (128B data + 16 pad): [A_hi 18432][A_lo 18432][B 18432]
#define A_ROWB    144
#define A_OFF_AHI 0
#define A_OFF_ALO 18432
#define A_OFF_B   36864
#define A_BUFST   55296
#define A_SMEMSZ  (2 * A_BUFST)     // 110592
// kernelB: BK=32, ROWB=80
#define ROWB 80
#define B_OFF_AHI 0
#define B_OFF_ALO 5120
#define B_OFF_BHI 10240
#define B_OFF_BLO 20480
#define B_BUFST   30720
#define B_SMEMSZ  (2 * B_BUFST)
// kernelC
#define C_OFF_AHI 0
#define C_OFF_ALO 2560
#define C_OFF_BHI 5120
#define C_OFF_BLO 15360
#define C_BUFST   25600
#define C_SMEMSZ  (2 * C_BUFST)

// =====================================================================
// kPrepAll: blocks [0,1024): w_gcn transpose->fp16; [1024,1280): gate weights
// =====================================================================
__global__ void kPrepAll(const float* __restrict__ wgcn,
                         const float* __restrict__ wz, const float* __restrict__ uz,
                         const float* __restrict__ wh, const float* __restrict__ uh)
{
    __shared__ float tile[32][33];
    const int c = threadIdx.x & 31, r = threadIdx.x >> 5;
    int bx = blockIdx.x;
    if (bx < 1024){
        const int k0 = (bx & 127) * 32, n0 = (bx >> 7) * 32;
#pragma unroll
        for (int i = 0; i < 4; i++)
            tile[r + 8*i][c] = wgcn[(size_t)(k0 + r + 8*i) * UN + n0 + c];
        __syncthreads();
#pragma unroll
        for (int i = 0; i < 4; i++){
            size_t o = (size_t)(n0 + r + 8*i) * NN + k0 + c;
            g_wth[o] = cvt1h(tile[c][r + 8*i]);
        }
    } else {
        bx -= 1024;
        const int k0 = (bx & 15) * 32, n0 = (bx >> 4) * 32;
#pragma unroll
        for (int i = 0; i < 4; i++){
            int kk = k0 + r + 8*i;
            int nn = n0 + c;
            const float* src = (kk < 256) ? ((nn < 256) ? wz : wh) : ((nn < 256) ? uz : uh);
            tile[r + 8*i][c] = src[(size_t)(kk & 255) * UN + (nn & 255)];
        }
        __syncthreads();
#pragma unroll
        for (int i = 0; i < 4; i++){
            float v = tile[c][r + 8*i];
            size_t o = (size_t)(n0 + r + 8*i) * 512 + k0 + c;
            split1h(v, g_gw_hi[o], g_gw_lo[o]);
        }
    }
}

// =====================================================================
// kernelA: partialG[ks] = adj_mix[m0:m0+128, ks*2048:+2048] @ w_gcn
// fp16 2-term; grid (32 m, 2 n, 2 ksplit) = 128 CTAs, BK=64, 32 stages.
// Per warp (2m x 4n): M64 x N32, 128 MMAs/stage.
// =====================================================================
#define KA_NST 32     // 2048 / 64

__global__ __launch_bounds__(256, 1) void kernelA(const float* __restrict__ adj,
                                                  const float* __restrict__ wap)
{
    extern __shared__ __align__(16) char smem[];
    const uint32_t sb = smem_u32(smem);
    const int tid = threadIdx.x, wid = tid >> 5, lane = tid & 31;
    const int g = lane >> 2, tig = lane & 3;
    const int m0 = blockIdx.x * 128, n0 = blockIdx.y * 128;
    const int kbase = blockIdx.z * 2048;
    const float w0 = wap[0], w1 = wap[1], w2 = wap[2];
    const size_t GS = (size_t)NN * NN;

    float acc[4][4][4];
#pragma unroll
    for (int a = 0; a < 4; a++)
#pragma unroll
        for (int b = 0; b < 4; b++)
#pragma unroll
            for (int c = 0; c < 4; c++) acc[a][b][c] = 0.f;

    float4 ra[4][3];

    // B tile: 128 n-rows x 64 k halves (128B). 4 cp.async per thread.
    auto issueB = [&](int t, int b){
#pragma unroll
        for (int j = 0; j < 4; j++){
            int f = j*256 + tid, row = f >> 3, c = f & 7;
            uint32_t daddr = sb + b*A_BUFST + A_OFF_B + row*A_ROWB + c*16;
            size_t go = (size_t)(n0 + row) * NN + kbase + t*64 + c*8;
            cpasync16(daddr, g_wth + go);
        }
        CP_COMMIT;
    };
    // A half-chunk h (32 k): 4 float4 loads per thread (128 rows x 8 quads)
    auto loadA = [&](int t, int h){
#pragma unroll
        for (int j = 0; j < 4; j++){
            int f = j*256 + tid, row = f >> 3, q = f & 7;
            const float* p = adj + (size_t)(m0 + row) * NN + kbase + t*64 + h*32 + q*4;
            ra[j][0] = __ldg((const float4*)p);
            ra[j][1] = __ldg((const float4*)(p + GS));
            ra[j][2] = __ldg((const float4*)(p + 2*GS));
        }
    };
    auto storeA = [&](int b, int h){
        char* base = smem + b*A_BUFST;
#pragma unroll
        for (int j = 0; j < 4; j++){
            int f = j*256 + tid, row = f >> 3, q = f & 7;
            float vx = fmaf(w0, ra[j][0].x, fmaf(w1, ra[j][1].x, w2*ra[j][2].x));
            float vy = fmaf(w0, ra[j][0].y, fmaf(w1, ra[j][1].y, w2*ra[j][2].y));
            float vz = fmaf(w0, ra[j][0].z, fmaf(w1, ra[j][1].z, w2*ra[j][2].z));
            float vw = fmaf(w0, ra[j][0].w, fmaf(w1, ra[j][1].w, w2*ra[j][2].w));
            uint32_t h0, l0, h1, l1;
            split2h(vx, vy, h0, l0);
            split2h(vz, vw, h1, l1);
            int off = row*A_ROWB + h*64 + q*8;
            *(uint2*)(base + A_OFF_AHI + off) = make_uint2(h0, h1);
            *(uint2*)(base + A_OFF_ALO + off) = make_uint2(l0, l1);
        }
    };

    const int am = (wid & 1) * 64 + g;
    const int bn = (wid >> 1) * 32 + g;

    // half-stage MMA: s in [s0, s0+2)
    auto mma_half = [&](const char* buf, int s0){
#pragma unroll
        for (int s = s0; s < s0 + 2; s++){
            const int ko = s * 32 + tig * 4;
            uint32_t bh[4][2];
#pragma unroll
            for (int ni = 0; ni < 4; ni++){
                const char* p = buf + A_OFF_B + (bn + ni*8) * A_ROWB + ko;
                bh[ni][0] = *(const uint32_t*)p;
                bh[ni][1] = *(const uint32_t*)(p + 16);
            }
#pragma unroll
            for (int mi = 0; mi < 4; mi++){
                const char* p = buf + A_OFF_AHI + (am + mi*16) * A_ROWB + ko;
                uint32_t ah[4] = { *(const uint32_t*)p,        *(const uint32_t*)(p + 8*A_ROWB),
                                   *(const uint32_t*)(p + 16), *(const uint32_t*)(p + 8*A_ROWB + 16) };
                const char* q = buf + A_OFF_ALO + (am + mi*16) * A_ROWB + ko;
                uint32_t al[4] = { *(const uint32_t*)q,        *(const uint32_t*)(q + 8*A_ROWB),
                                   *(const uint32_t*)(q + 16), *(const uint32_t*)(q + 8*A_ROWB + 16) };
#pragma unroll
                for (int ni = 0; ni < 4; ni++){
                    mma16816h(acc[mi][ni], ah, bh[ni]);
                    mma16816h(acc[mi][ni], al, bh[ni]);
                }
            }
        }
    };

    // prologue: fill buffer 0
    issueB(0, 0);
    loadA(0, 0); storeA(0, 0);
    loadA(0, 1); storeA(0, 1);
    CP_WAIT0; __syncthreads();

    for (int t = 0; t < KA_NST; t++){
        const int b = t & 1;
        const char* buf = smem + b*A_BUFST;
        if (t + 1 < KA_NST){
            issueB(t + 1, b ^ 1);
            loadA(t + 1, 0);
            mma_half(buf, 0);
            storeA(b ^ 1, 0);
            loadA(t + 1, 1);
            mma_half(buf, 2);
            storeA(b ^ 1, 1);
        } else {
            mma_half(buf, 0);
            mma_half(buf, 2);
        }
        CP_WAIT0; __syncthreads();
    }

    float* dst = g_partialG + (size_t)blockIdx.z * (NN * UN);
#pragma unroll
    for (int mi = 0; mi < 4; mi++){
#pragma unroll
        for (int ni = 0; ni < 4; ni++){
            int m = m0 + (wid & 1)*64 + mi*16 + g;
            int n = n0 + (wid >> 1)*32 + ni*8 + tig*2;
            *(float2*)(dst + (size_t)m * UN + n)       = make_float2(acc[mi][ni][0], acc[mi][ni][1]);
            *(float2*)(dst + (size_t)(m + 8) * UN + n) = make_float2(acc[mi][ni][2], acc[mi][ni][3]);
        }
    }
}

// =====================================================================
// kReduceGT: G = sum of 2 partials; transpose + fp16 split (vectorized)
// =====================================================================
__global__ void kReduceGT()
{
    __shared__ float tile[32][33];
    const int k0 = blockIdx.x * 32, n0 = blockIdx.y * 32;
    const int tid = threadIdx.x;
    {
        const int r = tid >> 3, q = tid & 7;
        size_t o = (size_t)(k0 + r) * UN + n0 + q*4;
        float4 a = *(const float4*)(g_partialG + o);
        float4 b = *(const float4*)(g_partialG + (size_t)NN*UN + o);
        tile[r][q*4+0] = a.x + b.x;
        tile[r][q*4+1] = a.y + b.y;
        tile[r][q*4+2] = a.z + b.z;
        tile[r][q*4+3] = a.w + b.w;
    }
    __syncthreads();
    {
        const int nr = tid >> 3, kq = tid & 7;
        u16 hh[4], ll[4];
#pragma unroll
        for (int j = 0; j < 4; j++)
            split1h(tile[kq*4+j][nr], hh[j], ll[j]);
        size_t o = (size_t)(n0 + nr) * NN + k0 + kq*4;
        *(uint2*)(g_Gt_hi + o) = *(uint2*)hh;
        *(uint2*)(g_Gt_lo + o) = *(uint2*)ll;
    }
}

// =====================================================================
// kernelB: partialX[ks] = inputs @ G  (fp16 3-term)
// grid (8 m, 2 n, 8 ksplit) = 128 CTAs
// =====================================================================
#define KB_NST 16

__global__ __launch_bounds__(256, 2) void kernelB(const float* __restrict__ inputs)
{
    extern __shared__ __align__(16) char smem[];
    const uint32_t sb = smem_u32(smem);
    const int tid = threadIdx.x, wid = tid >> 5, lane = tid & 31;
    const int g = lane >> 2, tig = lane & 3;
    const int m0 = blockIdx.x * 64, n0 = blockIdx.y * 128;
    const int kbase = blockIdx.z * 512;

    float acc[2][4][4];
#pragma unroll
    for (int a = 0; a < 2; a++)
#pragma unroll
        for (int b = 0; b < 4; b++)
#pragma unroll
            for (int c = 0; c < 4; c++) acc[a][b][c] = 0.f;

    float4 ra[2];

    auto issueB = [&](int t, int b){
#pragma unroll
        for (int j = 0; j < 2; j++){
            int f = j*256 + tid, row = f >> 2, c = f & 3;
            uint32_t daddr = sb + b*B_BUFST + row*ROWB + c*16;
            size_t go = (size_t)(n0 + row) * NN + kbase + t*32 + c*8;
            cpasync16(daddr + B_OFF_BHI, g_Gt_hi + go);
            cpasync16(daddr + B_OFF_BLO, g_Gt_lo + go);
        }
        CP_COMMIT;
    };
    auto loadA = [&](int t){
#pragma unroll
        for (int j = 0; j < 2; j++){
            int f = j*256 + tid, row = f >> 3, q = f & 7;
            ra[j] = __ldg((const float4*)(inputs + (size_t)(m0 + row) * NN + kbase + t*32 + q*4));
        }
    };
    auto storeA = [&](int b){
        char* base = smem + b*B_BUFST;
#pragma unroll
        for (int j = 0; j < 2; j++){
            int f = j*256 + tid, row = f >> 3, q = f & 7;
            uint32_t h0, l0, h1, l1;
            split2h(ra[j].x, ra[j].y, h0, l0);
            split2h(ra[j].z, ra[j].w, h1, l1);
            *(uint2*)(base + B_OFF_AHI + row*ROWB + q*8) = make_uint2(h0, h1);
            *(uint2*)(base + B_OFF_ALO + row*ROWB + q*8) = make_uint2(l0, l1);
        }
    };

    issueB(0, 0);
    loadA(0); storeA(0);
    CP_WAIT0; __syncthreads();

    const int am = (wid & 1) * 32 + g;
    const int bn = (wid >> 1) * 32 + g;

    for (int t = 0; t < KB_NST; t++){
        const int b = t & 1;
        if (t + 1 < KB_NST){ issueB(t + 1, b ^ 1); loadA(t + 1); }

        const char* buf = smem + b*B_BUFST;
#pragma unroll
        for (int s = 0; s < 2; s++){
            const int ko = s * 32 + tig * 4;
            uint32_t ah[2][4], al[2][4];
#pragma unroll
            for (int mi = 0; mi < 2; mi++){
                const char* pa = buf + B_OFF_AHI + (am + mi*16) * ROWB + ko;
                ah[mi][0] = *(const uint32_t*)pa;        ah[mi][1] = *(const uint32_t*)(pa + 8*ROWB);
                ah[mi][2] = *(const uint32_t*)(pa + 16); ah[mi][3] = *(const uint32_t*)(pa + 8*ROWB + 16);
                const char* ql = buf + B_OFF_ALO + (am + mi*16) * ROWB + ko;
                al[mi][0] = *(const uint32_t*)ql;        al[mi][1] = *(const uint32_t*)(ql + 8*ROWB);
                al[mi][2] = *(const uint32_t*)(ql + 16); al[mi][3] = *(const uint32_t*)(ql + 8*ROWB + 16);
            }
#pragma unroll
            for (int ni = 0; ni < 4; ni++){
                const char* pb = buf + B_OFF_BHI + (bn + ni*8) * ROWB + ko;
                uint32_t bh[2] = { *(const uint32_t*)pb, *(const uint32_t*)(pb + 16) };
                const char* qb = buf + B_OFF_BLO + (bn + ni*8) * ROWB + ko;
                uint32_t bl[2] = { *(const uint32_t*)qb, *(const uint32_t*)(qb + 16) };
#pragma unroll
                for (int mi = 0; mi < 2; mi++){
                    mma16816h(acc[mi][ni], ah[mi], bh);
                    mma16816h(acc[mi][ni], ah[mi], bl);
                    mma16816h(acc[mi][ni], al[mi], bh);
                }
            }
        }

        if (t + 1 < KB_NST) storeA(b ^ 1);
        CP_WAIT0; __syncthreads();
    }

    float* dst = g_partialX + (size_t)blockIdx.z * (BT * UN);
#pragma unroll
    for (int mi = 0; mi < 2; mi++){
        int m = m0 + am + mi*16;
#pragma unroll
        for (int ni = 0; ni < 4; ni++){
            int n = n0 + bn - g + ni*8 + tig*2;
            *(float2*)(dst + (size_t)m * UN + n)       = make_float2(acc[mi][ni][0], acc[mi][ni][1]);
            *(float2*)(dst + (size_t)(m + 8) * UN + n) = make_float2(acc[mi][ni][2], acc[mi][ni][3]);
        }
    }
}

// =====================================================================
// kernelC: fused GRU gate GEMM + epilogue; reduceX+relu folded into loadA.
// grid (16 m, 4 n) = 64 CTAs
// =====================================================================
#define KC_NST 16

__global__ __launch_bounds__(256, 2) void kernelC(const float* __restrict__ state,
    const float* __restrict__ bz, const float* __restrict__ bh,
    float* __restrict__ out)
{
    extern __shared__ __align__(16) char smem[];
    const uint32_t sb = smem_u32(smem);
    const int tid = threadIdx.x, wid = tid >> 5, lane = tid & 31;
    const int g = lane >> 2, tig = lane & 3;
    const int m0 = blockIdx.x * 32;
    const int n0 = blockIdx.y * 64;

    float accz[2][4], acch[2][4];
#pragma unroll
    for (int a = 0; a < 2; a++)
#pragma unroll
        for (int c = 0; c < 4; c++){ accz[a][c] = 0.f; acch[a][c] = 0.f; }

    const int arow = tid >> 3;
    const int aq   = tid & 7;
    float4 ra;

    auto issueB = [&](int t, int b){
#pragma unroll
        for (int j = 0; j < 2; j++){
            int f = j*256 + tid, r = f >> 2, c = f & 3;
            int nprime = (r < 64) ? (n0 + r) : (256 + n0 + (r - 64));
            uint32_t daddr = sb + b*C_BUFST + r*ROWB + c*16;
            size_t go = (size_t)nprime * 512 + t*32 + c*8;
            cpasync16(daddr + C_OFF_BHI, g_gw_hi + go);
            cpasync16(daddr + C_OFF_BLO, g_gw_lo + go);
        }
        CP_COMMIT;
    };
    auto loadA = [&](int t){
        int kp = t*32 + aq*4;
        if (kp < 256){
            // fused kReduceX: X = relu(sum of 8 partial planes)
            size_t o = (size_t)(m0 + arow) * UN + kp;
            float4 s = *(const float4*)(g_partialX + o);
#pragma unroll
            for (int pl = 1; pl < 8; pl++){
                float4 t4 = __ldg((const float4*)(g_partialX + (size_t)pl * (BT*UN) + o));
                s.x += t4.x; s.y += t4.y; s.z += t4.z; s.w += t4.w;
            }
            ra.x = fmaxf(s.x, 0.f); ra.y = fmaxf(s.y, 0.f);
            ra.z = fmaxf(s.z, 0.f); ra.w = fmaxf(s.w, 0.f);
        } else {
            ra = __ldg((const float4*)(state + (size_t)(m0 + arow) * UN + (kp - 256)));
        }
    };
    auto storeA = [&](int b){
        char* base = smem + b*C_BUFST;
        uint32_t h0, l0, h1, l1;
        split2h(ra.x, ra.y, h0, l0);
        split2h(ra.z, ra.w, h1, l1);
        *(uint2*)(base + C_OFF_AHI + arow*ROWB + aq*8) = make_uint2(h0, h1);
        *(uint2*)(base + C_OFF_ALO + arow*ROWB + aq*8) = make_uint2(l0, l1);
    };

    issueB(0, 0);
    loadA(0); storeA(0);
    CP_WAIT0; __syncthreads();

    const int am = (wid & 1) * 16 + g;
    const int bn = (wid >> 1) * 16;

    for (int t = 0; t < KC_NST; t++){
        const int b = t & 1;
        if (t + 1 < KC_NST){ issueB(t + 1, b ^ 1); loadA(t + 1); }

        const char* buf = smem + b*C_BUFST;
#pragma unroll
        for (int s = 0; s < 2; s++){
            const int ko = s * 32 + tig * 4;
            const char* pa = buf + C_OFF_AHI + am * ROWB + ko;
            uint32_t ah[4] = { *(const uint32_t*)pa,        *(const uint32_t*)(pa + 8*ROWB),
                               *(const uint32_t*)(pa + 16), *(const uint32_t*)(pa + 8*ROWB + 16) };
            const char* ql = buf + C_OFF_ALO + am * ROWB + ko;
            uint32_t al[4] = { *(const uint32_t*)ql,        *(const uint32_t*)(ql + 8*ROWB),
                               *(const uint32_t*)(ql + 16), *(const uint32_t*)(ql + 8*ROWB + 16) };
#pragma unroll
            for (int ni = 0; ni < 2; ni++){
                const char* pb = buf + C_OFF_BHI + (bn + g + ni*8) * ROWB + ko;
                uint32_t bhz[2] = { *(const uint32_t*)pb, *(const uint32_t*)(pb + 16) };
                const char* qb = buf + C_OFF_BLO + (bn + g + ni*8) * ROWB + ko;
                uint32_t blz[2] = { *(const uint32_t*)qb, *(const uint32_t*)(qb + 16) };
                mma16816h(accz[ni], ah, bhz);
                mma16816h(accz[ni], ah, blz);
                mma16816h(accz[ni], al, bhz);
                const char* ph = buf + C_OFF_BHI + (64 + bn + g + ni*8) * ROWB + ko;
                uint32_t bhh[2] = { *(const uint32_t*)ph, *(const uint32_t*)(ph + 16) };
                const char* qh = buf + C_OFF_BLO + (64 + bn + g + ni*8) * ROWB + ko;
                uint32_t blh[2] = { *(const uint32_t*)qh, *(const uint32_t*)(qh + 16) };
                mma16816h(acch[ni], ah, bhh);
                mma16816h(acch[ni], ah, blh);
                mma16816h(acch[ni], al, bhh);
            }
        }

        if (t + 1 < KC_NST) storeA(b ^ 1);
        CP_WAIT0; __syncthreads();
    }

#pragma unroll
    for (int ni = 0; ni < 2; ni++){
        int n = n0 + bn + ni*8 + tig*2;
        float2 bzv = *(const float2*)(bz + n);
        float2 bhv = *(const float2*)(bh + n);
#pragma unroll
        for (int half = 0; half < 2; half++){
            int m = m0 + am + half*8;
            float pz0 = accz[ni][half*2+0] + bzv.x;
            float pz1 = accz[ni][half*2+1] + bzv.y;
            float ph0 = acch[ni][half*2+0] + bhv.x;
            float ph1 = acch[ni][half*2+1] + bhv.y;
            float2 sv = *(const float2*)(state + (size_t)m * UN + n);
            float z0 = 1.0f / (1.0f + expf(-pz0));
            float z1 = 1.0f / (1.0f + expf(-pz1));
            float h0 = tanhf(ph0);
            float h1 = tanhf(ph1);
            float o0 = sv.x + z0 * (h0 - sv.x);
            float o1 = sv.y + z1 * (h1 - sv.y);
            *(float2*)(out + (size_t)m * UN + n) = make_float2(o0, o1);
        }
    }
}

// =====================================================================
extern "C" void kernel_launch(void* const* d_in, const int* in_sizes, int n_in,
                              void* d_out, int out_size)
{
    const float* inputs = (const float*)d_in[0];
    const float* state  = (const float*)d_in[1];
    const float* adj    = (const float*)d_in[2];
    const float* wa     = (const float*)d_in[3];
    const float* wgcn   = (const float*)d_in[4];
    const float* wz     = (const float*)d_in[5];
    const float* uz     = (const float*)d_in[6];
    const float* bz     = (const float*)d_in[7];
    const float* wh     = (const float*)d_in[8];
    const float* uh     = (const float*)d_in[9];
    const float* bh     = (const float*)d_in[10];
    float* out = (float*)d_out;

    cudaFuncSetAttribute(kernelA, cudaFuncAttributeMaxDynamicSharedMemorySize, A_SMEMSZ);
    cudaFuncSetAttribute(kernelB, cudaFuncAttributeMaxDynamicSharedMemorySize, B_SMEMSZ);
    cudaFuncSetAttribute(kernelC, cudaFuncAttributeMaxDynamicSharedMemorySize, C_SMEMSZ);

    kPrepAll<<<1280, 256>>>(wgcn, wz, uz, wh, uh);
    kernelA<<<dim3(32, 2, 2), 256, A_SMEMSZ>>>(adj, wa);
    kReduceGT<<<dim3(NN/32, UN/32), 256>>>();
    kernelB<<<dim3(8, 2, 8), 256, B_SMEMSZ>>>(inputs);
    kernelC<<<dim3(16, 4), 256, C_SMEMSZ>>>(state, bz, bh, out);
}